// round 4
// baseline (speedup 1.0000x reference)
#include <cuda_runtime.h>
#include <math.h>

#define BS 8
#define NP 2048
#define CD 12
#define FD 2
#define DD 24
#define KS 16
#define RPB 8
#define TPB 512
#define MPT 4
#define CAP 256
#define FULLMASK 0xffffffffu

// normalized features, d-major for coalesced m-loads: gFnT[b][d][m]
__device__ float gFnT[BS][DD][NP];

// ---------------------------------------------------------------------------
// prep: build normalized features (mimics reference fp32 arithmetic order) and
// write tgt_out (simple transposed copy of the flow slice).
// ---------------------------------------------------------------------------
__global__ void prep_kernel(const float* __restrict__ x, const int* __restrict__ flowp,
                            float* __restrict__ out) {
    int idx = blockIdx.x * blockDim.x + threadIdx.x;
    if (idx >= BS * NP) return;
    int b = idx >> 11;
    int n = idx & (NP - 1);
    int flow = flowp ? flowp[0] : 0;
    const float* xb = x + (size_t)b * (CD * FD * NP);

    float feats[DD];
#pragma unroll
    for (int f = 0; f < FD; f++)
#pragma unroll
        for (int c = 0; c < CD; c++)
            feats[f * CD + c] = xb[(c * FD + f) * NP + n];

    float ss = 0.f;
#pragma unroll
    for (int d = 0; d < DD; d++) ss = __fadd_rn(ss, __fmul_rn(feats[d], feats[d]));
    float denom = __fadd_rn(sqrtf(ss), 1e-8f);
#pragma unroll
    for (int d = 0; d < DD; d++)
        gFnT[b][d][n] = __fdiv_rn(feats[d], denom);

    float* out2 = out + (size_t)BS * NP * KS * CD;
#pragma unroll
    for (int c = 0; c < CD; c++)
        out2[(b * CD + c) * NP + n] = xb[(c * FD + flow) * NP + n];
}

// ---------------------------------------------------------------------------
// main: block = 512 threads, 8 query rows. Phase 1: register dots (8 rows x
// 4 m each via float4 loads). Phase 2: threshold from registers (per-warp
// bitonic -> block max), atomic compaction, warp-per-row exact top-16.
// No full score rows in smem -> 18KB smem, 2 CTA/SM by regs (32 warps).
// ---------------------------------------------------------------------------
__global__ void __launch_bounds__(TPB, 2) main_kernel(const float* __restrict__ x,
                                                      const int* __restrict__ flowp,
                                                      float* __restrict__ out) {
    __shared__ float s_q[DD * RPB];        // [d][r]
    __shared__ float s_T[RPB][16];         // per-warp 16th-largest lane-max
    __shared__ int   s_cnt[RPB];
    __shared__ float s_cv[RPB][CAP];
    __shared__ int   s_cm[RPB][CAP];
    __shared__ int   s_sel[RPB][KS];

    int blk = blockIdx.x;                  // BS * (NP/RPB) = 2048
    int b   = blk >> 8;
    int n0  = (blk & 255) * RPB;
    int tid = threadIdx.x;
    int wid = tid >> 5, lane = tid & 31;

    if (tid < DD * RPB) {
        int d = tid >> 3, r = tid & 7;
        s_q[tid] = gFnT[b][d][n0 + r];
    }
    if (tid < RPB) s_cnt[tid] = 0;
    __syncthreads();

    // ---------------- phase 1: dots (m = 4*tid + j) ----------------
    float acc[RPB][MPT];
#pragma unroll
    for (int r = 0; r < RPB; r++)
#pragma unroll
        for (int j = 0; j < MPT; j++) acc[r][j] = 0.f;

#pragma unroll 6
    for (int d = 0; d < DD; d++) {
        float4 fm = reinterpret_cast<const float4*>(&gFnT[b][d][0])[tid];
        float4 qa = *reinterpret_cast<const float4*>(&s_q[d * 8]);
        float4 qb = *reinterpret_cast<const float4*>(&s_q[d * 8 + 4]);
        float q[RPB] = {qa.x, qa.y, qa.z, qa.w, qb.x, qb.y, qb.z, qb.w};
        float f[MPT] = {fm.x, fm.y, fm.z, fm.w};
#pragma unroll
        for (int r = 0; r < RPB; r++)
#pragma unroll
            for (int j = 0; j < MPT; j++)
                acc[r][j] = fmaf(q[r], f[j], acc[r][j]);
    }

    // ---------------- phase 2a: per-warp thresholds ----------------
#pragma unroll
    for (int r = 0; r < RPB; r++) {
        float lm = fmaxf(fmaxf(acc[r][0], acc[r][1]), fmaxf(acc[r][2], acc[r][3]));
        float sv = lm;
#pragma unroll
        for (int k2 = 2; k2 <= 32; k2 <<= 1) {
#pragma unroll
            for (int j2 = k2 >> 1; j2 > 0; j2 >>= 1) {
                float o = __shfl_xor_sync(FULLMASK, sv, j2);
                bool up = ((lane & k2) == 0);
                bool lower = ((lane & j2) == 0);
                float mx = fmaxf(sv, o), mn = fminf(sv, o);
                sv = (up == lower) ? mx : mn;
            }
        }
        if (lane == 15) s_T[r][wid] = sv;   // 16th largest lane-max of this warp
    }
    __syncthreads();

    // ---------------- phase 2b: global threshold + compaction ----------------
#pragma unroll
    for (int r = 0; r < RPB; r++) {
        float tv = (lane < 16) ? s_T[r][lane] : -INFINITY;
#pragma unroll
        for (int off = 8; off > 0; off >>= 1)
            tv = fmaxf(tv, __shfl_xor_sync(FULLMASK, tv, off));
        float tg = __shfl_sync(FULLMASK, tv, 0);   // max of per-warp thresholds

        float svv[MPT]; int svm[MPT];
        int lc = 0;
#pragma unroll
        for (int j = 0; j < MPT; j++) {
            float v = acc[r][j];
            if (v >= tg) { svv[lc] = v; svm[lc] = 4 * tid + j; lc++; }
        }
        int scan = lc;
#pragma unroll
        for (int off = 1; off < 32; off <<= 1) {
            int nn = __shfl_up_sync(FULLMASK, scan, off);
            if (lane >= off) scan += nn;
        }
        int total = __shfl_sync(FULLMASK, scan, 31);
        int base = 0;
        if (lane == 31 && total > 0) base = atomicAdd(&s_cnt[r], total);
        base = __shfl_sync(FULLMASK, base, 31);
        int off0 = base + scan - lc;
        for (int t = 0; t < lc; t++) {
            int p = off0 + t;
            if (p < CAP) { s_cv[r][p] = svv[t]; s_cm[r][p] = svm[t]; }
        }
    }
    __syncthreads();

    // ---------------- phase 2c: warp-per-row exact top-16 + gather ----------
    if (wid < RPB) {
        int r = wid;
        int n = n0 + r;
        int cnt = s_cnt[r];
        float pv = INFINITY; int pm = -1;

        if (cnt <= CAP) {
            for (int k = 0; k < KS; k++) {
                float bv = -INFINITY; int bm = 0x7fffffff;
                for (int i = lane; i < cnt; i += 32) {
                    float v = s_cv[r][i]; int mi = s_cm[r][i];
                    bool elig = (v < pv) || (v == pv && mi > pm);
                    if (elig && ((v > bv) || (v == bv && mi < bm))) { bv = v; bm = mi; }
                }
#pragma unroll
                for (int off = 16; off > 0; off >>= 1) {
                    float ov = __shfl_down_sync(FULLMASK, bv, off);
                    int   om = __shfl_down_sync(FULLMASK, bm, off);
                    if ((ov > bv) || (ov == bv && om < bm)) { bv = ov; bm = om; }
                }
                bv = __shfl_sync(FULLMASK, bv, 0);
                bm = __shfl_sync(FULLMASK, bm, 0);
                pv = bv; pm = bm;
                if (lane == 0) s_sel[r][k] = bm;
            }
        } else {
            // overflow fallback (cold): recompute scores on the fly, exact.
            for (int k = 0; k < KS; k++) {
                float bv = -INFINITY; int bm = 0x7fffffff;
                for (int i = lane; i < NP; i += 32) {
                    float v = 0.f;
#pragma unroll
                    for (int d = 0; d < DD; d++)
                        v = fmaf(s_q[d * 8 + r], gFnT[b][d][i], v);
                    bool elig = (v < pv) || (v == pv && i > pm);
                    if (elig && ((v > bv) || (v == bv && i < bm))) { bv = v; bm = i; }
                }
#pragma unroll
                for (int off = 16; off > 0; off >>= 1) {
                    float ov = __shfl_down_sync(FULLMASK, bv, off);
                    int   om = __shfl_down_sync(FULLMASK, bm, off);
                    if ((ov > bv) || (ov == bv && om < bm)) { bv = ov; bm = om; }
                }
                bv = __shfl_sync(FULLMASK, bv, 0);
                bm = __shfl_sync(FULLMASK, bm, 0);
                pv = bv; pm = bm;
                if (lane == 0) s_sel[r][k] = bm;
            }
        }
        __syncwarp();

        // gather: sx_c[b][n][k][c] = x_c[b][c][flow][sel[k]]
        int flow = flowp ? flowp[0] : 0;
        const float* xb = x + (size_t)b * (CD * FD * NP);
        float* o1 = out + (size_t)(b * NP + n) * (KS * CD);
        for (int t = lane; t < KS * CD; t += 32) {
            int k = t / CD;
            int c = t - k * CD;
            int m = s_sel[r][k];
            o1[t] = xb[(c * FD + flow) * NP + m];
        }
    }
}

extern "C" void kernel_launch(void* const* d_in, const int* in_sizes, int n_in,
                              void* d_out, int out_size) {
    const float* x = (const float*)d_in[0];
    const int* flowp = (n_in >= 2) ? (const int*)d_in[1] : nullptr;
    float* out = (float*)d_out;

    prep_kernel<<<(BS * NP + 255) / 256, 256>>>(x, flowp, out);
    main_kernel<<<BS * (NP / RPB), TPB>>>(x, flowp, out);
}

// round 5
// speedup vs baseline: 6.7788x; 6.7788x over previous
#include <cuda_runtime.h>
#include <math.h>

#define BS 8
#define NP 2048
#define CD 12
#define FD 2
#define DD 24
#define KS 16
#define RPB 8
#define TPB 512
#define MPT 4
#define CAP 128
#define FULLMASK 0xffffffffu

// smem words: s_A 8*2048 | s_q 192 | s_cv 8*CAP | s_cm 8*CAP | s_sel 8*16
#define SMEM_WORDS (RPB*NP + DD*RPB + RPB*CAP + RPB*CAP + RPB*KS)
#define SMEM_BYTES (SMEM_WORDS * 4)

typedef unsigned long long ull;

// normalized features, d-major for coalesced m-loads: gFnT[b][d][m]
__device__ float gFnT[BS][DD][NP];

// ---------------------------------------------------------------------------
// prep: normalized features (reference fp32 arithmetic order) + tgt_out copy.
// ---------------------------------------------------------------------------
__global__ void prep_kernel(const float* __restrict__ x, const int* __restrict__ flowp,
                            float* __restrict__ out) {
    int idx = blockIdx.x * blockDim.x + threadIdx.x;
    if (idx >= BS * NP) return;
    int b = idx >> 11;
    int n = idx & (NP - 1);
    int flow = flowp ? flowp[0] : 0;
    const float* xb = x + (size_t)b * (CD * FD * NP);

    float feats[DD];
#pragma unroll
    for (int f = 0; f < FD; f++)
#pragma unroll
        for (int c = 0; c < CD; c++)
            feats[f * CD + c] = xb[(c * FD + f) * NP + n];

    float ss = 0.f;
#pragma unroll
    for (int d = 0; d < DD; d++) ss = __fadd_rn(ss, __fmul_rn(feats[d], feats[d]));
    float denom = __fadd_rn(sqrtf(ss), 1e-8f);
#pragma unroll
    for (int d = 0; d < DD; d++)
        gFnT[b][d][n] = __fdiv_rn(feats[d], denom);

    float* out2 = out + (size_t)BS * NP * KS * CD;
#pragma unroll
    for (int c = 0; c < CD; c++)
        out2[(b * CD + c) * NP + n] = xb[(c * FD + flow) * NP + n];
}

// orderable 64-bit key: (monotone float map) desc, then index asc
__device__ __forceinline__ ull make_key(float v, int idx) {
    unsigned u = __float_as_uint(v);
    u = (u & 0x80000000u) ? ~u : (u | 0x80000000u);
    return ((ull)u << 32) | (unsigned)(NP - 1 - idx);
}
__device__ __forceinline__ int key_idx(ull k) {
    return NP - 1 - (int)(k & 0xffffffffu);
}

// full bitonic sort of 32 keys, descending (lane 0 = largest)
__device__ __forceinline__ ull sort32_desc(ull v, int lane) {
#pragma unroll
    for (int k2 = 2; k2 <= 32; k2 <<= 1) {
#pragma unroll
        for (int j2 = k2 >> 1; j2 > 0; j2 >>= 1) {
            ull o = __shfl_xor_sync(FULLMASK, v, j2);
            bool up = ((lane & k2) == 0);
            bool low = ((lane & j2) == 0);
            ull mx = v > o ? v : o, mn = v > o ? o : v;
            v = (up == low) ? mx : mn;
        }
    }
    return v;
}

// merge: best (desc-sorted) with ch (desc-sorted) -> top-32 of union, desc
__device__ __forceinline__ ull merge32_desc(ull best, ull ch, int lane) {
    ull o = __shfl_sync(FULLMASK, ch, 31 - lane);
    ull v = best > o ? best : o;          // bitonic sequence holding top-32
#pragma unroll
    for (int j2 = 16; j2 > 0; j2 >>= 1) {
        ull w = __shfl_xor_sync(FULLMASK, v, j2);
        bool low = ((lane & j2) == 0);
        ull mx = v > w ? v : w, mn = v > w ? w : v;
        v = low ? mx : mn;
    }
    return v;
}

// ---------------------------------------------------------------------------
// main: 512 thr, 8 rows. Phase 1: float4 register dots (8 rows x 4 m / thr)
// -> s_A. Phase 2: warps 0..7, one row each: threshold (bitonic of lane
// maxima), ballot compaction, 64-bit-key bitonic sort for exact ordered
// top-16, then gather.
// ---------------------------------------------------------------------------
__global__ void __launch_bounds__(TPB, 2) main_kernel(const float* __restrict__ x,
                                                      const int* __restrict__ flowp,
                                                      float* __restrict__ out) {
    extern __shared__ float sm[];
    float* s_A   = sm;                          // [RPB][NP]
    float* s_q   = s_A + RPB * NP;              // [DD][RPB]
    float* s_cv  = s_q + DD * RPB;              // [RPB][CAP]
    int*   s_cm  = (int*)(s_cv + RPB * CAP);    // [RPB][CAP]
    int*   s_sel = s_cm + RPB * CAP;            // [RPB][KS]

    int blk = blockIdx.x;                  // BS * (NP/RPB) = 2048
    int b   = blk >> 8;
    int n0  = (blk & 255) * RPB;
    int tid = threadIdx.x;
    int wid = tid >> 5, lane = tid & 31;

    if (tid < DD * RPB) {
        int d = tid >> 3, r = tid & 7;
        s_q[tid] = gFnT[b][d][n0 + r];
    }
    __syncthreads();

    // ---------------- phase 1: dots (m = 4*tid + j) ----------------
    float acc[RPB][MPT];
#pragma unroll
    for (int r = 0; r < RPB; r++)
#pragma unroll
        for (int j = 0; j < MPT; j++) acc[r][j] = 0.f;

#pragma unroll 6
    for (int d = 0; d < DD; d++) {
        float4 fm = reinterpret_cast<const float4*>(&gFnT[b][d][0])[tid];
        float4 qa = *reinterpret_cast<const float4*>(&s_q[d * 8]);
        float4 qb = *reinterpret_cast<const float4*>(&s_q[d * 8 + 4]);
        float q[RPB] = {qa.x, qa.y, qa.z, qa.w, qb.x, qb.y, qb.z, qb.w};
        float f[MPT] = {fm.x, fm.y, fm.z, fm.w};
#pragma unroll
        for (int r = 0; r < RPB; r++)
#pragma unroll
            for (int j = 0; j < MPT; j++)
                acc[r][j] = fmaf(q[r], f[j], acc[r][j]);
    }

#pragma unroll
    for (int r = 0; r < RPB; r++)
        reinterpret_cast<float4*>(s_A + r * NP)[tid] =
            make_float4(acc[r][0], acc[r][1], acc[r][2], acc[r][3]);
    __syncthreads();

    // ---------------- phase 2: warp-per-row ----------------
    if (wid < RPB) {
        int r = wid;
        int n = n0 + r;
        const float* Ar = s_A + r * NP;
        float* cv = s_cv + r * CAP;
        int*   cm = s_cm + r * CAP;

        // per-lane max over 64 strided elements
        float lmax = -INFINITY;
#pragma unroll 8
        for (int j = 0; j < NP / 32; j++)
            lmax = fmaxf(lmax, Ar[lane + 32 * j]);

        // threshold: 16th largest of the 32 lane maxima (bitonic desc)
        float sv = lmax;
#pragma unroll
        for (int k2 = 2; k2 <= 32; k2 <<= 1) {
#pragma unroll
            for (int j2 = k2 >> 1; j2 > 0; j2 >>= 1) {
                float o = __shfl_xor_sync(FULLMASK, sv, j2);
                bool up = ((lane & k2) == 0);
                bool low = ((lane & j2) == 0);
                float mx = fmaxf(sv, o), mn = fminf(sv, o);
                sv = (up == low) ? mx : mn;
            }
        }
        float T = __shfl_sync(FULLMASK, sv, 15);

        // ballot compaction of survivors (v >= T); >=16 guaranteed
        int cnt = 0;
        for (int j = 0; j < NP / 32; j++) {
            int mi = lane + 32 * j;
            float v = Ar[mi];
            bool p = (v >= T);
            unsigned bal = __ballot_sync(FULLMASK, p);
            if (p) {
                int pos = cnt + __popc(bal & ((1u << lane) - 1u));
                if (pos < CAP) { cv[pos] = v; cm[pos] = mi; }
            }
            cnt += __popc(bal);
        }
        __syncwarp();

        ull best;
        if (cnt <= CAP) {
            int cn = cnt;
            ull k0 = (lane < cn) ? make_key(cv[lane], cm[lane]) : 0ULL;
            best = sort32_desc(k0, lane);
            for (int c0 = 32; c0 < cn; c0 += 32) {
                int i = c0 + lane;
                ull kc = (i < cn) ? make_key(cv[i], cm[i]) : 0ULL;
                kc = sort32_desc(kc, lane);
                best = merge32_desc(best, kc, lane);
            }
        } else {
            // cold exact fallback: chunk-merge over the full row
            ull k0 = make_key(Ar[lane], lane);
            best = sort32_desc(k0, lane);
            for (int c0 = 32; c0 < NP; c0 += 32) {
                int i = c0 + lane;
                ull kc = sort32_desc(make_key(Ar[i], i), lane);
                best = merge32_desc(best, kc, lane);
            }
        }

        if (lane < KS) s_sel[r * KS + lane] = key_idx(best);
        __syncwarp();

        // gather: sx_c[b][n][k][c] = x_c[b][c][flow][sel[k]]
        int flow = flowp ? flowp[0] : 0;
        const float* xb = x + (size_t)b * (CD * FD * NP);
        float* o1 = out + (size_t)(b * NP + n) * (KS * CD);
        for (int t = lane; t < KS * CD; t += 32) {
            int k = t / CD;
            int c = t - k * CD;
            int m = s_sel[r * KS + k];
            o1[t] = xb[(c * FD + flow) * NP + m];
        }
    }
}

extern "C" void kernel_launch(void* const* d_in, const int* in_sizes, int n_in,
                              void* d_out, int out_size) {
    const float* x = (const float*)d_in[0];
    const int* flowp = (n_in >= 2) ? (const int*)d_in[1] : nullptr;
    float* out = (float*)d_out;

    prep_kernel<<<(BS * NP + 255) / 256, 256>>>(x, flowp, out);

    cudaFuncSetAttribute(main_kernel, cudaFuncAttributeMaxDynamicSharedMemorySize, SMEM_BYTES);
    main_kernel<<<BS * (NP / RPB), TPB, SMEM_BYTES>>>(x, flowp, out);
}